// round 1
// baseline (speedup 1.0000x reference)
#include <cuda_runtime.h>

#define NB 4
#define SQ 1024
#define DM 1280
#define NH 16
#define HD 80
#define MTOT (NB*SQ)      // 4096
#define NQKV (3*DM)       // 3840

// Scratch (allocation-free rule: __device__ globals)
__device__ float g_q[NB*NH*SQ*HD];
__device__ float g_k[NB*NH*SQ*HD];
__device__ float g_v[NB*NH*SQ*HD];
__device__ float g_ctx[MTOT*DM];

// ---------------------------------------------------------------------------
// GEMM: C[m,n] = sum_k A[m,k] * W[n,k] + bias[n]
// Tiles: 128x128x16, 256 threads, 8x8 per thread (two 4-wide chunks per dim).
// QKV=true : A = x, scatter epilogue into g_q/g_k/g_v head-major.
// QKV=false: A = g_ctx, dense epilogue into Cout.
// ---------------------------------------------------------------------------
template<bool QKV>
__global__ void __launch_bounds__(256) gemm_kernel(
    const float* __restrict__ A, const float* __restrict__ W,
    const float* __restrict__ bias, float* __restrict__ Cout)
{
    __shared__ float As[16][128];
    __shared__ float Bs[16][128];
    const int bx = blockIdx.x, by = blockIdx.y;
    const int t  = threadIdx.x;
    const int lr = t >> 2;            // 0..63
    const int lc = (t & 3) << 2;      // 0,4,8,12
    const int ty = t >> 4;            // 0..15
    const int tx = t & 15;            // 0..15

    const float* Ab = (QKV ? A : (const float*)g_ctx) + (size_t)(by * 128) * DM;
    const float* Wb = W + (size_t)(bx * 128) * DM;

    float acc[8][8];
    #pragma unroll
    for (int i = 0; i < 8; i++)
        #pragma unroll
        for (int j = 0; j < 8; j++) acc[i][j] = 0.f;

    for (int k0 = 0; k0 < DM; k0 += 16) {
        #pragma unroll
        for (int p = 0; p < 2; p++) {
            float4 av = *(const float4*)(Ab + (size_t)(p*64 + lr) * DM + k0 + lc);
            As[lc+0][p*64+lr] = av.x; As[lc+1][p*64+lr] = av.y;
            As[lc+2][p*64+lr] = av.z; As[lc+3][p*64+lr] = av.w;
            float4 bv = *(const float4*)(Wb + (size_t)(p*64 + lr) * DM + k0 + lc);
            Bs[lc+0][p*64+lr] = bv.x; Bs[lc+1][p*64+lr] = bv.y;
            Bs[lc+2][p*64+lr] = bv.z; Bs[lc+3][p*64+lr] = bv.w;
        }
        __syncthreads();
        #pragma unroll
        for (int kk = 0; kk < 16; kk++) {
            float4 a0 = *(const float4*)&As[kk][ty*4];
            float4 a1 = *(const float4*)&As[kk][64 + ty*4];
            float4 b0 = *(const float4*)&Bs[kk][tx*4];
            float4 b1 = *(const float4*)&Bs[kk][64 + tx*4];
            float a[8] = {a0.x,a0.y,a0.z,a0.w,a1.x,a1.y,a1.z,a1.w};
            float b[8] = {b0.x,b0.y,b0.z,b0.w,b1.x,b1.y,b1.z,b1.w};
            #pragma unroll
            for (int i = 0; i < 8; i++)
                #pragma unroll
                for (int j = 0; j < 8; j++) acc[i][j] += a[i] * b[j];
        }
        __syncthreads();
    }

    #pragma unroll
    for (int ih = 0; ih < 2; ih++)
        #pragma unroll
        for (int ii = 0; ii < 4; ii++) {
            const int m = by*128 + ih*64 + ty*4 + ii;
            #pragma unroll
            for (int jh = 0; jh < 2; jh++) {
                const int n = bx*128 + jh*64 + tx*4;
                float4 v;
                v.x = acc[ih*4+ii][jh*4+0] + bias[n+0];
                v.y = acc[ih*4+ii][jh*4+1] + bias[n+1];
                v.z = acc[ih*4+ii][jh*4+2] + bias[n+2];
                v.w = acc[ih*4+ii][jh*4+3] + bias[n+3];
                if (QKV) {
                    // n -> (sel, head, d); a 4-chunk never crosses a head (80 % 4 == 0,
                    // chunk base is a multiple of 4)
                    const int sel = n / DM;
                    const int r   = n - sel * DM;
                    const int h   = r / HD;
                    const int dd  = r - h * HD;
                    const int bb  = m >> 10;
                    const int ss  = m & (SQ - 1);
                    float* dst = (sel == 0) ? g_q : ((sel == 1) ? g_k : g_v);
                    *(float4*)&dst[(((size_t)bb * NH + h) * SQ + ss) * HD + dd] = v;
                } else {
                    *(float4*)&Cout[(size_t)m * DM + n] = v;
                }
            }
        }
}

// ---------------------------------------------------------------------------
// RoPE (in place on g_q, g_k). One thread per (b,h,s,d<40) pair.
// out[d]    = t[d]*cos[d]       - t[d+40]*sin[d]
// out[d+40] = t[d+40]*cos[d+40] + t[d]*sin[d+40]
// ---------------------------------------------------------------------------
__global__ void __launch_bounds__(256) rope_kernel(
    const float* __restrict__ cosp, const float* __restrict__ sinp)
{
    const int idx  = blockIdx.x * 256 + threadIdx.x;   // < NB*NH*SQ*40
    const int d    = idx % 40;
    const int rest = idx / 40;
    const int ss   = rest & (SQ - 1);
    const int bh   = rest >> 10;
    const size_t base = ((size_t)bh * SQ + ss) * HD;
    const float c1 = cosp[ss*HD + d],      s1 = sinp[ss*HD + d];
    const float c2 = cosp[ss*HD + d + 40], s2 = sinp[ss*HD + d + 40];
    float q1 = g_q[base + d], q2 = g_q[base + d + 40];
    g_q[base + d]      = q1*c1 - q2*s1;
    g_q[base + d + 40] = q2*c2 + q1*s2;
    float k1 = g_k[base + d], k2 = g_k[base + d + 40];
    g_k[base + d]      = k1*c1 - k2*s1;
    g_k[base + d + 40] = k2*c2 + k1*s2;
}

// ---------------------------------------------------------------------------
// Flash attention: block = (q-tile of 64 rows, bh). Bc = 64, online softmax.
// S-phase: 16x16 threads, 4x4 microtile. PV-phase: 4 threads/row, 20 cols each.
// ---------------------------------------------------------------------------
#define QP 68   // smem pitch for transposed Q/K and for S (keeps 16B alignment)
#define ATTN_SMEM ((80*QP*2 + 64*HD + 64*QP + 128) * 4)

__global__ void __launch_bounds__(256) attn_kernel()
{
    extern __shared__ float sm[];
    float* Qt = sm;                 // [80][QP]  Q transposed, pre-scaled
    float* Kt = Qt + 80*QP;         // [80][QP]  K transposed
    float* Vs = Kt + 80*QP;         // [64][80]
    float* Ss = Vs + 64*HD;         // [64][QP]  P tile
    float* alpha_s = Ss + 64*QP;    // [64]
    float* l_s     = alpha_s + 64;  // [64]

    const int qt = blockIdx.x;      // 0..15
    const int bh = blockIdx.y;      // 0..63
    const int t  = threadIdx.x;
    const int ty = t >> 4, tx = t & 15;   // S-phase mapping
    const int rw = t >> 2, qd = t & 3;    // PV-phase mapping
    const float scale = 0.11180339887498948f;  // 1/sqrt(80)

    const float* Qb = g_q + ((size_t)bh * SQ + qt * 64) * HD;
    const float* Kb = g_k + (size_t)bh * SQ * HD;
    const float* Vb = g_v + (size_t)bh * SQ * HD;

    for (int idx = t; idx < 64 * HD; idx += 256) {
        const int r = idx / HD, d = idx - r * HD;
        Qt[d*QP + r] = Qb[idx] * scale;
    }

    float m_i[4], l_i[4];
    #pragma unroll
    for (int i = 0; i < 4; i++) { m_i[i] = -1e30f; l_i[i] = 0.f; }
    float o[5][4];
    #pragma unroll
    for (int c = 0; c < 5; c++)
        #pragma unroll
        for (int j = 0; j < 4; j++) o[c][j] = 0.f;

    for (int kt = 0; kt < 16; kt++) {
        const float* Kp = Kb + (size_t)kt * 64 * HD;
        const float* Vp = Vb + (size_t)kt * 64 * HD;
        for (int idx = t; idx < 64 * HD; idx += 256) {
            const int r = idx / HD, d = idx - r * HD;
            Kt[d*QP + r] = Kp[idx];
            Vs[idx]      = Vp[idx];
        }
        __syncthreads();

        // S = (Q*scale) @ K^T for this 64x64 tile
        float s[4][4];
        #pragma unroll
        for (int i = 0; i < 4; i++)
            #pragma unroll
            for (int j = 0; j < 4; j++) s[i][j] = 0.f;
        for (int d = 0; d < HD; d++) {
            float4 a = *(const float4*)&Qt[d*QP + ty*4];
            float4 b = *(const float4*)&Kt[d*QP + tx*4];
            float av[4] = {a.x, a.y, a.z, a.w};
            float bv[4] = {b.x, b.y, b.z, b.w};
            #pragma unroll
            for (int i = 0; i < 4; i++)
                #pragma unroll
                for (int j = 0; j < 4; j++) s[i][j] += av[i] * bv[j];
        }

        // online softmax; row reductions via shfl within the 16-lane tx group
        #pragma unroll
        for (int i = 0; i < 4; i++) {
            float mx = fmaxf(fmaxf(s[i][0], s[i][1]), fmaxf(s[i][2], s[i][3]));
            #pragma unroll
            for (int off = 8; off >= 1; off >>= 1)
                mx = fmaxf(mx, __shfl_xor_sync(0xffffffffu, mx, off));
            const float mnew = fmaxf(m_i[i], mx);
            const float al   = __expf(m_i[i] - mnew);
            float4 p;
            p.x = __expf(s[i][0] - mnew);
            p.y = __expf(s[i][1] - mnew);
            p.z = __expf(s[i][2] - mnew);
            p.w = __expf(s[i][3] - mnew);
            float rs = p.x + p.y + p.z + p.w;
            #pragma unroll
            for (int off = 8; off >= 1; off >>= 1)
                rs += __shfl_xor_sync(0xffffffffu, rs, off);
            m_i[i] = mnew;
            l_i[i] = l_i[i] * al + rs;
            *(float4*)&Ss[(ty*4 + i)*QP + tx*4] = p;
            if (tx == 0) alpha_s[ty*4 + i] = al;
        }
        __syncthreads();

        // O = O*alpha + P @ V   (PV mapping: row rw, cols qd*4 + 16*c)
        const float al = alpha_s[rw];
        #pragma unroll
        for (int c = 0; c < 5; c++)
            #pragma unroll
            for (int j = 0; j < 4; j++) o[c][j] *= al;

        #pragma unroll 4
        for (int j = 0; j < 64; j++) {
            const float av = Ss[rw*QP + j];
            #pragma unroll
            for (int c = 0; c < 5; c++) {
                float4 bv = *(const float4*)&Vs[j*HD + qd*4 + c*16];
                o[c][0] += av * bv.x; o[c][1] += av * bv.y;
                o[c][2] += av * bv.z; o[c][3] += av * bv.w;
            }
        }
        __syncthreads();
    }

    if (tx == 0) {
        #pragma unroll
        for (int i = 0; i < 4; i++) l_s[ty*4 + i] = l_i[i];
    }
    __syncthreads();

    const float inv = 1.f / l_s[rw];
    const int b = bh >> 4, h = bh & 15;
    const size_t orow = ((size_t)b * SQ + qt*64 + rw) * DM + h * HD;
    #pragma unroll
    for (int c = 0; c < 5; c++) {
        float4 v;
        v.x = o[c][0]*inv; v.y = o[c][1]*inv; v.z = o[c][2]*inv; v.w = o[c][3]*inv;
        *(float4*)&g_ctx[orow + qd*4 + c*16] = v;
    }
}

// ---------------------------------------------------------------------------
extern "C" void kernel_launch(void* const* d_in, const int* in_sizes, int n_in,
                              void* d_out, int out_size)
{
    (void)in_sizes; (void)n_in; (void)out_size;
    const float* x     = (const float*)d_in[0];
    const float* cosp  = (const float*)d_in[1];
    const float* sinp  = (const float*)d_in[2];
    const float* Wqkv  = (const float*)d_in[3];
    const float* bqkv  = (const float*)d_in[4];
    const float* Wproj = (const float*)d_in[5];
    const float* bproj = (const float*)d_in[6];
    float* out = (float*)d_out;

    cudaFuncSetAttribute(attn_kernel,
                         cudaFuncAttributeMaxDynamicSharedMemorySize, ATTN_SMEM);

    // 1) QKV GEMM + bias, scatter to head-major q/k/v
    gemm_kernel<true><<<dim3(NQKV/128, MTOT/128), 256>>>(x, Wqkv, bqkv, nullptr);
    // 2) RoPE on q, k
    rope_kernel<<<(NB*NH*SQ*40)/256, 256>>>(cosp, sinp);
    // 3) attention -> g_ctx ([b, s, h*HD] layout)
    attn_kernel<<<dim3(SQ/64, NB*NH), 256, ATTN_SMEM>>>();
    // 4) output projection + bias -> d_out
    gemm_kernel<false><<<dim3(DM/128, MTOT/128), 256>>>(nullptr, Wproj, bproj, out);
}

// round 3
// speedup vs baseline: 1.3690x; 1.3690x over previous
#include <cuda_runtime.h>
#include <cuda_bf16.h>
#include <cstdint>

#define NB 4
#define SQ 1024
#define DM 1280
#define NH 16
#define HD 80
#define MTOT (NB*SQ)      // 4096
#define NQKV (3*DM)       // 3840

// Scratch (allocation-free rule: __device__ globals)
__device__ float g_q[NB*NH*SQ*HD];
__device__ float g_k[NB*NH*SQ*HD];
__device__ float g_v[NB*NH*SQ*HD];
__device__ float g_ctx[MTOT*DM];

// ===========================================================================
// helpers
// ===========================================================================
__device__ __forceinline__ uint32_t s2u(const void* p) {
    uint32_t a;
    asm("{ .reg .u64 t; cvta.to.shared.u64 t, %1; cvt.u32.u64 %0, t; }"
        : "=r"(a) : "l"(p));
    return a;
}

__device__ __forceinline__ void ldm_x4(uint32_t* r, uint32_t addr) {
    asm volatile("ldmatrix.sync.aligned.m8n8.x4.shared.b16 {%0,%1,%2,%3}, [%4];"
        : "=r"(r[0]), "=r"(r[1]), "=r"(r[2]), "=r"(r[3]) : "r"(addr));
}

__device__ __forceinline__ void mma16816(float* c, const uint32_t* a,
                                         uint32_t b0, uint32_t b1) {
    asm volatile(
        "mma.sync.aligned.m16n8k16.row.col.f32.bf16.bf16.f32 "
        "{%0,%1,%2,%3}, {%4,%5,%6,%7}, {%8,%9}, {%0,%1,%2,%3};"
        : "+f"(c[0]), "+f"(c[1]), "+f"(c[2]), "+f"(c[3])
        : "r"(a[0]), "r"(a[1]), "r"(a[2]), "r"(a[3]), "r"(b0), "r"(b1));
}

__device__ __forceinline__ uint32_t packbf(float a, float b) {
    __nv_bfloat162 t = __floats2bfloat162_rn(a, b);
    return *reinterpret_cast<uint32_t*>(&t);
}

// ===========================================================================
// Tensor-core GEMM via mma.sync bf16, 3-term split (hi*hi + lo*hi + hi*lo).
// C[m,n] = sum_k A[m,k] * W[n,k] + bias[n]
// Tile 128x128, K-stage 32 fp32. Smem: Ah/Al/Bh/Bl bf16, pitch 80B, dbl-buf.
// ===========================================================================
#define KSTAGE 32
#define NIT (DM / KSTAGE)          // 40
#define PITCH 80                   // 64B data + 16B pad (conflict-free ldmatrix)
#define MAT_BYTES (128 * PITCH)    // 10240
#define STAGE_BYTES (4 * MAT_BYTES)
#define GEMM_DSMEM (2 * STAGE_BYTES)

template<bool QKV>
__global__ void __launch_bounds__(256) gemm_tc(
    const float* __restrict__ A, const float* __restrict__ W,
    const float* __restrict__ bias, float* __restrict__ Cout)
{
    extern __shared__ char dsm_raw[];
    const uint32_t base = s2u(dsm_raw);

    const int tid  = threadIdx.x;
    const int wid  = tid >> 5, lane = tid & 31;
    const int bx = blockIdx.x, by = blockIdx.y;
    const int row = tid >> 1, half = tid & 1;   // LDG/STS mapping
    const int wm = wid >> 1, wn = wid & 1;      // warp tile: 32(M) x 64(N)

    const float* Abase = (QKV ? A : (const float*)g_ctx)
                         + (size_t)(by * 128 + row) * DM + half * 16;
    const float* Bbase = W + (size_t)(bx * 128 + row) * DM + half * 16;

    float4 ra[4], rb[4];
    auto LDG = [&](int it) {
        const float* ap = Abase + it * KSTAGE;
        const float* bp = Bbase + it * KSTAGE;
        #pragma unroll
        for (int j = 0; j < 4; j++) {
            ra[j] = *(const float4*)(ap + j * 4);
            rb[j] = *(const float4*)(bp + j * 4);
        }
    };

    auto STS = [&](int stg) {
        const uint32_t sb = base + stg * STAGE_BYTES;
        const uint32_t off = (uint32_t)(row * PITCH + half * 32);
        float fa[16], fb[16];
        #pragma unroll
        for (int j = 0; j < 4; j++) {
            fa[4*j+0]=ra[j].x; fa[4*j+1]=ra[j].y; fa[4*j+2]=ra[j].z; fa[4*j+3]=ra[j].w;
            fb[4*j+0]=rb[j].x; fb[4*j+1]=rb[j].y; fb[4*j+2]=rb[j].z; fb[4*j+3]=rb[j].w;
        }
        uint32_t ah[8], al[8], bh[8], bl[8];
        #pragma unroll
        for (int p = 0; p < 8; p++) {
            float h0 = __bfloat162float(__float2bfloat16_rn(fa[2*p]));
            float h1 = __bfloat162float(__float2bfloat16_rn(fa[2*p+1]));
            ah[p] = packbf(h0, h1);
            al[p] = packbf(fa[2*p] - h0, fa[2*p+1] - h1);
            float g0 = __bfloat162float(__float2bfloat16_rn(fb[2*p]));
            float g1 = __bfloat162float(__float2bfloat16_rn(fb[2*p+1]));
            bh[p] = packbf(g0, g1);
            bl[p] = packbf(fb[2*p] - g0, fb[2*p+1] - g1);
        }
        #pragma unroll
        for (int v = 0; v < 2; v++) {
            asm volatile("st.shared.v4.b32 [%0], {%1,%2,%3,%4};"
                :: "r"(sb + off + v*16), "r"(ah[4*v]), "r"(ah[4*v+1]), "r"(ah[4*v+2]), "r"(ah[4*v+3]) : "memory");
            asm volatile("st.shared.v4.b32 [%0], {%1,%2,%3,%4};"
                :: "r"(sb + MAT_BYTES + off + v*16), "r"(al[4*v]), "r"(al[4*v+1]), "r"(al[4*v+2]), "r"(al[4*v+3]) : "memory");
            asm volatile("st.shared.v4.b32 [%0], {%1,%2,%3,%4};"
                :: "r"(sb + 2*MAT_BYTES + off + v*16), "r"(bh[4*v]), "r"(bh[4*v+1]), "r"(bh[4*v+2]), "r"(bh[4*v+3]) : "memory");
            asm volatile("st.shared.v4.b32 [%0], {%1,%2,%3,%4};"
                :: "r"(sb + 3*MAT_BYTES + off + v*16), "r"(bl[4*v]), "r"(bl[4*v+1]), "r"(bl[4*v+2]), "r"(bl[4*v+3]) : "memory");
        }
    };

    float acc[2][8][4];
    #pragma unroll
    for (int i = 0; i < 2; i++)
        #pragma unroll
        for (int j = 0; j < 8; j++)
            #pragma unroll
            for (int q = 0; q < 4; q++) acc[i][j][q] = 0.f;

    LDG(0); STS(0); __syncthreads();

    for (int it = 0; it < NIT; ++it) {
        const int cur = it & 1;
        if (it + 1 < NIT) LDG(it + 1);

        const uint32_t sb = base + cur * STAGE_BYTES;
        #pragma unroll
        for (int kc = 0; kc < 2; kc++) {
            // A fragments (hi & lo): lanes 0-15 rows, 16-31 rows at k+8
            uint32_t Ah[2][4], Al[2][4];
            #pragma unroll
            for (int mf = 0; mf < 2; mf++) {
                const uint32_t aoff =
                    (uint32_t)((wm*32 + mf*16 + (lane & 15)) * PITCH
                               + kc*32 + (lane >> 4) * 16);
                ldm_x4(Ah[mf], sb + aoff);
                ldm_x4(Al[mf], sb + MAT_BYTES + aoff);
            }
            // B fragments (hi & lo): 4 x4 loads cover 64 n-cols
            uint32_t Bh[4][4], Bl[4][4];
            #pragma unroll
            for (int g = 0; g < 4; g++) {
                const int quad = lane >> 3;
                const uint32_t boff =
                    (uint32_t)((wn*64 + g*16 + (quad >> 1) * 8 + (lane & 7)) * PITCH
                               + kc*32 + (quad & 1) * 16);
                ldm_x4(Bh[g], sb + 2*MAT_BYTES + boff);
                ldm_x4(Bl[g], sb + 3*MAT_BYTES + boff);
            }
            // 3 passes: hi*hi, lo*hi, hi*lo
            #pragma unroll
            for (int mf = 0; mf < 2; mf++)
                #pragma unroll
                for (int nb = 0; nb < 8; nb++) {
                    const int g = nb >> 1, h2 = (nb & 1) * 2;
                    mma16816(acc[mf][nb], Ah[mf], Bh[g][h2], Bh[g][h2+1]);
                    mma16816(acc[mf][nb], Al[mf], Bh[g][h2], Bh[g][h2+1]);
                    mma16816(acc[mf][nb], Ah[mf], Bl[g][h2], Bl[g][h2+1]);
                }
        }
        __syncthreads();
        if (it + 1 < NIT) { STS(cur ^ 1); __syncthreads(); }
    }

    // Epilogue: write fragments directly (float2 chunks), bias + scatter
    #pragma unroll
    for (int mf = 0; mf < 2; mf++)
        #pragma unroll
        for (int nb = 0; nb < 8; nb++)
            #pragma unroll
            for (int ci = 0; ci < 2; ci++) {
                const int m = by*128 + wm*32 + mf*16 + (lane >> 2) + ci*8;
                const int n = bx*128 + wn*64 + nb*8 + (lane & 3) * 2;
                float2 v;
                v.x = acc[mf][nb][2*ci+0] + bias[n];
                v.y = acc[mf][nb][2*ci+1] + bias[n+1];
                if (QKV) {
                    const int sel = n / DM;
                    const int r2  = n - sel * DM;
                    const int h   = r2 / HD;
                    const int dd  = r2 - h * HD;
                    const int bb  = m >> 10;
                    const int ss  = m & (SQ - 1);
                    float* dst = (sel == 0) ? g_q : ((sel == 1) ? g_k : g_v);
                    *(float2*)&dst[(((size_t)bb * NH + h) * SQ + ss) * HD + dd] = v;
                } else {
                    *(float2*)&Cout[(size_t)m * DM + n] = v;
                }
            }
}

// ---------------------------------------------------------------------------
// RoPE (in place on g_q, g_k)
// ---------------------------------------------------------------------------
__global__ void __launch_bounds__(256) rope_kernel(
    const float* __restrict__ cosp, const float* __restrict__ sinp)
{
    const int idx  = blockIdx.x * 256 + threadIdx.x;   // < NB*NH*SQ*40
    const int d    = idx % 40;
    const int rest = idx / 40;
    const int ss   = rest & (SQ - 1);
    const int bh   = rest >> 10;
    const size_t base = ((size_t)bh * SQ + ss) * HD;
    const float c1 = cosp[ss*HD + d],      s1 = sinp[ss*HD + d];
    const float c2 = cosp[ss*HD + d + 40], s2 = sinp[ss*HD + d + 40];
    float q1 = g_q[base + d], q2 = g_q[base + d + 40];
    g_q[base + d]      = q1*c1 - q2*s1;
    g_q[base + d + 40] = q2*c2 + q1*s2;
    float k1 = g_k[base + d], k2 = g_k[base + d + 40];
    g_k[base + d]      = k1*c1 - k2*s1;
    g_k[base + d + 40] = k2*c2 + k1*s2;
}

// ---------------------------------------------------------------------------
// Flash attention (SIMT, unchanged this round)
// ---------------------------------------------------------------------------
#define QP 68
#define ATTN_SMEM ((80*QP*2 + 64*HD + 64*QP + 128) * 4)

__global__ void __launch_bounds__(256) attn_kernel()
{
    extern __shared__ char dsm_raw[];
    float* sm = (float*)dsm_raw;
    float* Qt = sm;
    float* Kt = Qt + 80*QP;
    float* Vs = Kt + 80*QP;
    float* Ss = Vs + 64*HD;
    float* alpha_s = Ss + 64*QP;
    float* l_s     = alpha_s + 64;

    const int qt = blockIdx.x;
    const int bh = blockIdx.y;
    const int t  = threadIdx.x;
    const int ty = t >> 4, tx = t & 15;
    const int rw = t >> 2, qd = t & 3;
    const float scale = 0.11180339887498948f;

    const float* Qb = g_q + ((size_t)bh * SQ + qt * 64) * HD;
    const float* Kb = g_k + (size_t)bh * SQ * HD;
    const float* Vb = g_v + (size_t)bh * SQ * HD;

    for (int idx = t; idx < 64 * HD; idx += 256) {
        const int r = idx / HD, d = idx - r * HD;
        Qt[d*QP + r] = Qb[idx] * scale;
    }

    float m_i[4], l_i[4];
    #pragma unroll
    for (int i = 0; i < 4; i++) { m_i[i] = -1e30f; l_i[i] = 0.f; }
    float o[5][4];
    #pragma unroll
    for (int c = 0; c < 5; c++)
        #pragma unroll
        for (int j = 0; j < 4; j++) o[c][j] = 0.f;

    for (int kt = 0; kt < 16; kt++) {
        const float* Kp = Kb + (size_t)kt * 64 * HD;
        const float* Vp = Vb + (size_t)kt * 64 * HD;
        for (int idx = t; idx < 64 * HD; idx += 256) {
            const int r = idx / HD, d = idx - r * HD;
            Kt[d*QP + r] = Kp[idx];
            Vs[idx]      = Vp[idx];
        }
        __syncthreads();

        float s[4][4];
        #pragma unroll
        for (int i = 0; i < 4; i++)
            #pragma unroll
            for (int j = 0; j < 4; j++) s[i][j] = 0.f;
        for (int d = 0; d < HD; d++) {
            float4 a = *(const float4*)&Qt[d*QP + ty*4];
            float4 b = *(const float4*)&Kt[d*QP + tx*4];
            float av[4] = {a.x, a.y, a.z, a.w};
            float bv[4] = {b.x, b.y, b.z, b.w};
            #pragma unroll
            for (int i = 0; i < 4; i++)
                #pragma unroll
                for (int j = 0; j < 4; j++) s[i][j] += av[i] * bv[j];
        }

        #pragma unroll
        for (int i = 0; i < 4; i++) {
            float mx = fmaxf(fmaxf(s[i][0], s[i][1]), fmaxf(s[i][2], s[i][3]));
            #pragma unroll
            for (int off = 8; off >= 1; off >>= 1)
                mx = fmaxf(mx, __shfl_xor_sync(0xffffffffu, mx, off));
            const float mnew = fmaxf(m_i[i], mx);
            const float al   = __expf(m_i[i] - mnew);
            float4 p;
            p.x = __expf(s[i][0] - mnew);
            p.y = __expf(s[i][1] - mnew);
            p.z = __expf(s[i][2] - mnew);
            p.w = __expf(s[i][3] - mnew);
            float rs = p.x + p.y + p.z + p.w;
            #pragma unroll
            for (int off = 8; off >= 1; off >>= 1)
                rs += __shfl_xor_sync(0xffffffffu, rs, off);
            m_i[i] = mnew;
            l_i[i] = l_i[i] * al + rs;
            *(float4*)&Ss[(ty*4 + i)*QP + tx*4] = p;
            if (tx == 0) alpha_s[ty*4 + i] = al;
        }
        __syncthreads();

        const float al = alpha_s[rw];
        #pragma unroll
        for (int c = 0; c < 5; c++)
            #pragma unroll
            for (int j = 0; j < 4; j++) o[c][j] *= al;

        #pragma unroll 4
        for (int j = 0; j < 64; j++) {
            const float av = Ss[rw*QP + j];
            #pragma unroll
            for (int c = 0; c < 5; c++) {
                float4 bv = *(const float4*)&Vs[j*HD + qd*4 + c*16];
                o[c][0] += av * bv.x; o[c][1] += av * bv.y;
                o[c][2] += av * bv.z; o[c][3] += av * bv.w;
            }
        }
        __syncthreads();
    }

    if (tx == 0) {
        #pragma unroll
        for (int i = 0; i < 4; i++) l_s[ty*4 + i] = l_i[i];
    }
    __syncthreads();

    const float inv = 1.f / l_s[rw];
    const int b = bh >> 4, h = bh & 15;
    const size_t orow = ((size_t)b * SQ + qt*64 + rw) * DM + h * HD;
    #pragma unroll
    for (int c = 0; c < 5; c++) {
        float4 v;
        v.x = o[c][0]*inv; v.y = o[c][1]*inv; v.z = o[c][2]*inv; v.w = o[c][3]*inv;
        *(float4*)&g_ctx[orow + qd*4 + c*16] = v;
    }
}

// ---------------------------------------------------------------------------
extern "C" void kernel_launch(void* const* d_in, const int* in_sizes, int n_in,
                              void* d_out, int out_size)
{
    (void)in_sizes; (void)n_in; (void)out_size;
    const float* x     = (const float*)d_in[0];
    const float* cosp  = (const float*)d_in[1];
    const float* sinp  = (const float*)d_in[2];
    const float* Wqkv  = (const float*)d_in[3];
    const float* bqkv  = (const float*)d_in[4];
    const float* Wproj = (const float*)d_in[5];
    const float* bproj = (const float*)d_in[6];
    float* out = (float*)d_out;

    cudaFuncSetAttribute(gemm_tc<true>,
                         cudaFuncAttributeMaxDynamicSharedMemorySize, GEMM_DSMEM);
    cudaFuncSetAttribute(gemm_tc<false>,
                         cudaFuncAttributeMaxDynamicSharedMemorySize, GEMM_DSMEM);
    cudaFuncSetAttribute(attn_kernel,
                         cudaFuncAttributeMaxDynamicSharedMemorySize, ATTN_SMEM);

    // 1) QKV GEMM + bias, scatter to head-major q/k/v (mma.sync bf16 x3)
    gemm_tc<true><<<dim3(NQKV/128, MTOT/128), 256, GEMM_DSMEM>>>(x, Wqkv, bqkv, nullptr);
    // 2) RoPE on q, k
    rope_kernel<<<(NB*NH*SQ*40)/256, 256>>>(cosp, sinp);
    // 3) attention -> g_ctx ([b, s, h*HD] layout)
    attn_kernel<<<dim3(SQ/64, NB*NH), 256, ATTN_SMEM>>>();
    // 4) output projection + bias -> d_out
    gemm_tc<false><<<dim3(DM/128, MTOT/128), 256, GEMM_DSMEM>>>(nullptr, Wproj, bproj, out);
}

// round 4
// speedup vs baseline: 2.9029x; 2.1205x over previous
#include <cuda_runtime.h>
#include <cuda_bf16.h>
#include <cstdint>

#define NB 4
#define SQ 1024
#define DM 1280
#define NH 16
#define HD 80
#define MTOT (NB*SQ)      // 4096
#define NQKV (3*DM)       // 3840

// ---------------------------------------------------------------------------
// Scratch (__device__ globals; allocation-free rule)
// ---------------------------------------------------------------------------
__device__ float g_q[NB*NH*SQ*HD];
__device__ float g_k[NB*NH*SQ*HD];

__device__ __nv_bfloat16 xh_g[MTOT*DM],  xl_g[MTOT*DM];
__device__ __nv_bfloat16 wqh_g[NQKV*DM], wql_g[NQKV*DM];
__device__ __nv_bfloat16 wph_g[DM*DM],   wpl_g[DM*DM];
__device__ __nv_bfloat16 qh_g[NB*NH*SQ*HD], ql_g[NB*NH*SQ*HD];
__device__ __nv_bfloat16 kh_g[NB*NH*SQ*HD], kl_g[NB*NH*SQ*HD];
__device__ __nv_bfloat16 vh_g[NB*NH*SQ*HD], vl_g[NB*NH*SQ*HD];
__device__ __nv_bfloat16 ch_g[MTOT*DM],  cl_g[MTOT*DM];

// ---------------------------------------------------------------------------
// helpers
// ---------------------------------------------------------------------------
__device__ __forceinline__ uint32_t s2u(const void* p) {
    uint32_t a;
    asm("{ .reg .u64 t; cvta.to.shared.u64 t, %1; cvt.u32.u64 %0, t; }"
        : "=r"(a) : "l"(p));
    return a;
}
__device__ __forceinline__ void ldm_x4(uint32_t* r, uint32_t addr) {
    asm volatile("ldmatrix.sync.aligned.m8n8.x4.shared.b16 {%0,%1,%2,%3}, [%4];"
        : "=r"(r[0]), "=r"(r[1]), "=r"(r[2]), "=r"(r[3]) : "r"(addr));
}
__device__ __forceinline__ void ldm_x4_t(uint32_t* r, uint32_t addr) {
    asm volatile("ldmatrix.sync.aligned.m8n8.x4.trans.shared.b16 {%0,%1,%2,%3}, [%4];"
        : "=r"(r[0]), "=r"(r[1]), "=r"(r[2]), "=r"(r[3]) : "r"(addr));
}
__device__ __forceinline__ void mma16816(float* c, const uint32_t* a,
                                         uint32_t b0, uint32_t b1) {
    asm volatile(
        "mma.sync.aligned.m16n8k16.row.col.f32.bf16.bf16.f32 "
        "{%0,%1,%2,%3}, {%4,%5,%6,%7}, {%8,%9}, {%0,%1,%2,%3};"
        : "+f"(c[0]), "+f"(c[1]), "+f"(c[2]), "+f"(c[3])
        : "r"(a[0]), "r"(a[1]), "r"(a[2]), "r"(a[3]), "r"(b0), "r"(b1));
}
__device__ __forceinline__ uint32_t packbf(float a, float b) {
    __nv_bfloat162 t = __floats2bfloat162_rn(a, b);
    return *reinterpret_cast<uint32_t*>(&t);
}
__device__ __forceinline__ void cpasync16(uint32_t dst, const void* src) {
    asm volatile("cp.async.ca.shared.global [%0], [%1], 16;"
        :: "r"(dst), "l"(src) : "memory");
}
#define CP_COMMIT() asm volatile("cp.async.commit_group;" ::: "memory")
#define CP_WAIT0()  asm volatile("cp.async.wait_group 0;" ::: "memory")
#define CP_WAIT1()  asm volatile("cp.async.wait_group 1;" ::: "memory")

// ---------------------------------------------------------------------------
// fp32 -> bf16 hi/lo split
// ---------------------------------------------------------------------------
__global__ void __launch_bounds__(256) split_kernel(
    const float* __restrict__ src, __nv_bfloat16* __restrict__ hi,
    __nv_bfloat16* __restrict__ lo, int n4)
{
    const int i = blockIdx.x * 256 + threadIdx.x;
    if (i >= n4) return;
    float4 v = ((const float4*)src)[i];
    __nv_bfloat16 h0 = __float2bfloat16_rn(v.x), h1 = __float2bfloat16_rn(v.y);
    __nv_bfloat16 h2 = __float2bfloat16_rn(v.z), h3 = __float2bfloat16_rn(v.w);
    ((__nv_bfloat162*)hi)[2*i+0] = __nv_bfloat162(h0, h1);
    ((__nv_bfloat162*)hi)[2*i+1] = __nv_bfloat162(h2, h3);
    ((__nv_bfloat162*)lo)[2*i+0] = __floats2bfloat162_rn(
        v.x - __bfloat162float(h0), v.y - __bfloat162float(h1));
    ((__nv_bfloat162*)lo)[2*i+1] = __floats2bfloat162_rn(
        v.z - __bfloat162float(h2), v.w - __bfloat162float(h3));
}

// ===========================================================================
// GEMM: C[m,n] = sum_k A[m,k]*W[n,k] + bias[n], via pre-split bf16 + mma.sync
// Tile 128x128, K-stage 32, 3-stage cp.async pipeline, pitch-80 smem.
// QKV=true: scatter q,k fp32 head-major + v bf16 hi/lo. false: dense fp32 out.
// ===========================================================================
#define KSTAGE 32
#define NIT (DM / KSTAGE)          // 40
#define PITCH 80
#define MAT_BYTES (128 * PITCH)    // 10240
#define STAGE_BYTES (4 * MAT_BYTES)
#define GEMM_DSMEM (3 * STAGE_BYTES)   // 122880

template<bool QKV>
__global__ void __launch_bounds__(256) gemm_bf16(
    const __nv_bfloat16* __restrict__ Ah_g, const __nv_bfloat16* __restrict__ Al_g,
    const __nv_bfloat16* __restrict__ Bh_g, const __nv_bfloat16* __restrict__ Bl_g,
    const float* __restrict__ bias, float* __restrict__ Cout)
{
    extern __shared__ char dsm_raw[];
    const uint32_t base = s2u(dsm_raw);

    const int tid  = threadIdx.x;
    const int wid  = tid >> 5, lane = tid & 31;
    const int bx = blockIdx.x, by = blockIdx.y;
    const int wm = wid >> 1, wn = wid & 1;      // warp tile: 32(M) x 64(N)

    const __nv_bfloat16* bases[4] = {
        Ah_g + (size_t)(by * 128) * DM, Al_g + (size_t)(by * 128) * DM,
        Bh_g + (size_t)(bx * 128) * DM, Bl_g + (size_t)(bx * 128) * DM };

    auto ISSUE = [&](int it) {
        const uint32_t sb = base + (it % 3) * STAGE_BYTES;
        #pragma unroll
        for (int j = 0; j < 8; j++) {
            const int idx = tid + 256 * j;
            const int mat = idx >> 9;
            const int rem = idx & 511;
            const int r = rem >> 2, c = rem & 3;
            const uint32_t dst = sb + mat * MAT_BYTES + r * PITCH + c * 16;
            const __nv_bfloat16* src = bases[mat] + (size_t)r * DM + it * KSTAGE + c * 8;
            cpasync16(dst, src);
        }
        CP_COMMIT();
    };

    float acc[2][8][4];
    #pragma unroll
    for (int i = 0; i < 2; i++)
        #pragma unroll
        for (int j = 0; j < 8; j++)
            #pragma unroll
            for (int q = 0; q < 4; q++) acc[i][j][q] = 0.f;

    ISSUE(0); ISSUE(1);

    for (int it = 0; it < NIT; ++it) {
        if (it == NIT - 1) { CP_WAIT0(); } else { CP_WAIT1(); }
        __syncthreads();
        if (it + 2 < NIT) ISSUE(it + 2);

        const uint32_t sb = base + (it % 3) * STAGE_BYTES;
        #pragma unroll
        for (int kc = 0; kc < 2; kc++) {
            uint32_t Ah[2][4], Al[2][4];
            #pragma unroll
            for (int mf = 0; mf < 2; mf++) {
                const uint32_t aoff =
                    (uint32_t)((wm*32 + mf*16 + (lane & 15)) * PITCH
                               + kc*32 + (lane >> 4) * 16);
                ldm_x4(Ah[mf], sb + aoff);
                ldm_x4(Al[mf], sb + MAT_BYTES + aoff);
            }
            uint32_t Bh[4][4], Bl[4][4];
            #pragma unroll
            for (int g = 0; g < 4; g++) {
                const int quad = lane >> 3;
                const uint32_t boff =
                    (uint32_t)((wn*64 + g*16 + (quad >> 1) * 8 + (lane & 7)) * PITCH
                               + kc*32 + (quad & 1) * 16);
                ldm_x4(Bh[g], sb + 2*MAT_BYTES + boff);
                ldm_x4(Bl[g], sb + 3*MAT_BYTES + boff);
            }
            #pragma unroll
            for (int mf = 0; mf < 2; mf++)
                #pragma unroll
                for (int nb = 0; nb < 8; nb++) {
                    const int g = nb >> 1, h2 = (nb & 1) * 2;
                    mma16816(acc[mf][nb], Ah[mf], Bh[g][h2], Bh[g][h2+1]);
                    mma16816(acc[mf][nb], Al[mf], Bh[g][h2], Bh[g][h2+1]);
                    mma16816(acc[mf][nb], Ah[mf], Bl[g][h2], Bl[g][h2+1]);
                }
        }
        __syncthreads();
    }

    // Epilogue
    #pragma unroll
    for (int mf = 0; mf < 2; mf++)
        #pragma unroll
        for (int nb = 0; nb < 8; nb++)
            #pragma unroll
            for (int ci = 0; ci < 2; ci++) {
                const int m = by*128 + wm*32 + mf*16 + (lane >> 2) + ci*8;
                const int n = bx*128 + wn*64 + nb*8 + (lane & 3) * 2;
                float2 v;
                v.x = acc[mf][nb][2*ci+0] + bias[n];
                v.y = acc[mf][nb][2*ci+1] + bias[n+1];
                if (QKV) {
                    const int sel = n / DM;
                    const int r2  = n - sel * DM;
                    const int h   = r2 / HD;
                    const int dd  = r2 - h * HD;
                    const int bb  = m >> 10;
                    const int ss  = m & (SQ - 1);
                    const size_t di = (((size_t)bb * NH + h) * SQ + ss) * HD + dd;
                    if (sel == 0)      *(float2*)&g_q[di] = v;
                    else if (sel == 1) *(float2*)&g_k[di] = v;
                    else {
                        __nv_bfloat16 h0 = __float2bfloat16_rn(v.x);
                        __nv_bfloat16 h1 = __float2bfloat16_rn(v.y);
                        *(__nv_bfloat162*)&vh_g[di] = __nv_bfloat162(h0, h1);
                        *(__nv_bfloat162*)&vl_g[di] = __floats2bfloat162_rn(
                            v.x - __bfloat162float(h0), v.y - __bfloat162float(h1));
                    }
                } else {
                    *(float2*)&Cout[(size_t)m * DM + n] = v;
                }
            }
}

// ---------------------------------------------------------------------------
// RoPE: read g_q/g_k fp32, write rotated bf16 hi/lo
// ---------------------------------------------------------------------------
__global__ void __launch_bounds__(256) rope_kernel(
    const float* __restrict__ cosp, const float* __restrict__ sinp)
{
    const int idx  = blockIdx.x * 256 + threadIdx.x;   // < NB*NH*SQ*40
    const int d    = idx % 40;
    const int rest = idx / 40;
    const int ss   = rest & (SQ - 1);
    const int bh   = rest >> 10;
    const size_t base = ((size_t)bh * SQ + ss) * HD;
    const float c1 = cosp[ss*HD + d],      s1 = sinp[ss*HD + d];
    const float c2 = cosp[ss*HD + d + 40], s2 = sinp[ss*HD + d + 40];

    float q1 = g_q[base + d], q2 = g_q[base + d + 40];
    float o1 = q1*c1 - q2*s1;
    float o2 = q2*c2 + q1*s2;
    __nv_bfloat16 h;
    h = __float2bfloat16_rn(o1); qh_g[base+d]    = h; ql_g[base+d]    = __float2bfloat16_rn(o1 - __bfloat162float(h));
    h = __float2bfloat16_rn(o2); qh_g[base+d+40] = h; ql_g[base+d+40] = __float2bfloat16_rn(o2 - __bfloat162float(h));

    float k1 = g_k[base + d], k2 = g_k[base + d + 40];
    o1 = k1*c1 - k2*s1;
    o2 = k2*c2 + k1*s2;
    h = __float2bfloat16_rn(o1); kh_g[base+d]    = h; kl_g[base+d]    = __float2bfloat16_rn(o1 - __bfloat162float(h));
    h = __float2bfloat16_rn(o2); kh_g[base+d+40] = h; kl_g[base+d+40] = __float2bfloat16_rn(o2 - __bfloat162float(h));
}

// ===========================================================================
// Flash attention on mma.sync. CTA = (qt 64 rows, bh), 4 warps (16 rows each).
// S = 3-pass split; softmax in fragments; PV = 3-pass with trans-ldmatrix V.
// Writes ch/cl bf16 hi/lo directly (proj input).
// ===========================================================================
#define APITCH 176                       // bytes per 80-elem bf16 row (+pad)
#define AQH 0
#define AQL (64*APITCH)                  // 11264
#define AKH (2*64*APITCH)
#define AKL (3*64*APITCH)
#define AVH (4*64*APITCH)
#define AVL (5*64*APITCH)
#define ATTN_SMEM (6*64*APITCH)          // 67584

__global__ void __launch_bounds__(128) attn_tc()
{
    extern __shared__ char dsm_raw[];
    const uint32_t base = s2u(dsm_raw);

    const int tid = threadIdx.x;
    const int w = tid >> 5, lane = tid & 31;
    const int qt = blockIdx.x, bh = blockIdx.y;
    const int b = bh >> 4, h = bh & 15;
    const float scale = 0.11180339887498948f;  // 1/sqrt(80)

    // Q tile load (once): 1280 x 16B chunks (hi 640 + lo 640)
    {
        const size_t qrow0 = (size_t)bh * SQ + qt * 64;
        #pragma unroll
        for (int j = 0; j < 10; j++) {
            const int idx = tid + 128 * j;     // 0..1279
            const int mat = idx / 640;
            const int rem = idx - mat * 640;
            const int r = rem / 10, c = rem - r * 10;
            const uint32_t dst = base + (mat ? AQL : AQH) + r * APITCH + c * 16;
            const __nv_bfloat16* src = (mat ? ql_g : qh_g) + (qrow0 + r) * HD + c * 8;
            cpasync16(dst, src);
        }
        CP_COMMIT();
    }

    float oacc[10][4];
    #pragma unroll
    for (int i = 0; i < 10; i++)
        #pragma unroll
        for (int j = 0; j < 4; j++) oacc[i][j] = 0.f;
    float m0 = -1e30f, m1 = -1e30f, l0 = 0.f, l1 = 0.f;

    for (int kt = 0; kt < 16; kt++) {
        // K/V tile load: 2560 chunks
        {
            const size_t krow0 = (size_t)bh * SQ + kt * 64;
            const __nv_bfloat16* srcs[4] = { kh_g, kl_g, vh_g, vl_g };
            const uint32_t dsts[4] = { AKH, AKL, AVH, AVL };
            #pragma unroll
            for (int j = 0; j < 20; j++) {
                const int idx = tid + 128 * j;   // 0..2559
                const int mat = idx / 640;
                const int rem = idx - mat * 640;
                const int r = rem / 10, c = rem - r * 10;
                cpasync16(base + dsts[mat] + r * APITCH + c * 16,
                          srcs[mat] + (krow0 + r) * HD + c * 8);
            }
            CP_COMMIT();
        }
        CP_WAIT0();
        __syncthreads();

        // ---- S = Q K^T (64x64), 3-pass split ----
        float sacc[8][4];
        #pragma unroll
        for (int i = 0; i < 8; i++)
            #pragma unroll
            for (int j = 0; j < 4; j++) sacc[i][j] = 0.f;

        #pragma unroll
        for (int kc = 0; kc < 5; kc++) {
            uint32_t Aah[4], Aal[4];
            const uint32_t aoff =
                (uint32_t)((w*16 + (lane & 15)) * APITCH + kc*32 + (lane >> 4) * 16);
            ldm_x4(Aah, base + AQH + aoff);
            ldm_x4(Aal, base + AQL + aoff);
            #pragma unroll
            for (int g = 0; g < 4; g++) {
                const int quad = lane >> 3;
                const uint32_t boff =
                    (uint32_t)((g*16 + (quad >> 1) * 8 + (lane & 7)) * APITCH
                               + kc*32 + (quad & 1) * 16);
                uint32_t Bbh[4], Bbl[4];
                ldm_x4(Bbh, base + AKH + boff);
                ldm_x4(Bbl, base + AKL + boff);
                #pragma unroll
                for (int hh = 0; hh < 2; hh++) {
                    const int nb = g*2 + hh;
                    mma16816(sacc[nb], Aah, Bbh[2*hh], Bbh[2*hh+1]);
                    mma16816(sacc[nb], Aal, Bbh[2*hh], Bbh[2*hh+1]);
                    mma16816(sacc[nb], Aah, Bbl[2*hh], Bbl[2*hh+1]);
                }
            }
        }

        // ---- online softmax on fragments (rows r0 = lane>>2, r1 = r0+8) ----
        #pragma unroll
        for (int nb = 0; nb < 8; nb++)
            #pragma unroll
            for (int j = 0; j < 4; j++) sacc[nb][j] *= scale;

        float mx0 = -1e30f, mx1 = -1e30f;
        #pragma unroll
        for (int nb = 0; nb < 8; nb++) {
            mx0 = fmaxf(mx0, fmaxf(sacc[nb][0], sacc[nb][1]));
            mx1 = fmaxf(mx1, fmaxf(sacc[nb][2], sacc[nb][3]));
        }
        mx0 = fmaxf(mx0, __shfl_xor_sync(0xffffffffu, mx0, 1));
        mx0 = fmaxf(mx0, __shfl_xor_sync(0xffffffffu, mx0, 2));
        mx1 = fmaxf(mx1, __shfl_xor_sync(0xffffffffu, mx1, 1));
        mx1 = fmaxf(mx1, __shfl_xor_sync(0xffffffffu, mx1, 2));

        const float mn0 = fmaxf(m0, mx0), mn1 = fmaxf(m1, mx1);
        const float al0 = __expf(m0 - mn0), al1 = __expf(m1 - mn1);
        m0 = mn0; m1 = mn1;

        float rs0 = 0.f, rs1 = 0.f;
        #pragma unroll
        for (int nb = 0; nb < 8; nb++) {
            sacc[nb][0] = __expf(sacc[nb][0] - m0);
            sacc[nb][1] = __expf(sacc[nb][1] - m0);
            sacc[nb][2] = __expf(sacc[nb][2] - m1);
            sacc[nb][3] = __expf(sacc[nb][3] - m1);
            rs0 += sacc[nb][0] + sacc[nb][1];
            rs1 += sacc[nb][2] + sacc[nb][3];
        }
        rs0 += __shfl_xor_sync(0xffffffffu, rs0, 1);
        rs0 += __shfl_xor_sync(0xffffffffu, rs0, 2);
        rs1 += __shfl_xor_sync(0xffffffffu, rs1, 1);
        rs1 += __shfl_xor_sync(0xffffffffu, rs1, 2);
        l0 = l0 * al0 + rs0;
        l1 = l1 * al1 + rs1;

        #pragma unroll
        for (int nb = 0; nb < 10; nb++) {
            oacc[nb][0] *= al0; oacc[nb][1] *= al0;
            oacc[nb][2] *= al1; oacc[nb][3] *= al1;
        }

        // ---- O += P @ V, 3-pass (Ph*Vh + Pl*Vh + Ph*Vl) ----
        #pragma unroll
        for (int kc = 0; kc < 4; kc++) {
            uint32_t pah[4], pal[4];
            #pragma unroll
            for (int half2i = 0; half2i < 2; half2i++) {
                const int nb = 2*kc + half2i;
                float f0 = sacc[nb][0], f1 = sacc[nb][1];
                float f2 = sacc[nb][2], f3 = sacc[nb][3];
                float h0 = __bfloat162float(__float2bfloat16_rn(f0));
                float h1 = __bfloat162float(__float2bfloat16_rn(f1));
                float h2 = __bfloat162float(__float2bfloat16_rn(f2));
                float h3 = __bfloat162float(__float2bfloat16_rn(f3));
                pah[2*half2i+0] = packbf(h0, h1);
                pah[2*half2i+1] = packbf(h2, h3);
                pal[2*half2i+0] = packbf(f0 - h0, f1 - h1);
                pal[2*half2i+1] = packbf(f2 - h2, f3 - h3);
            }
            // reorder: a0=(r0,klo) a1=(r1,klo) a2=(r0,khi) a3=(r1,khi)
            uint32_t Pa_h[4] = { pah[0], pah[1], pah[2], pah[3] };
            uint32_t Pa_l[4] = { pal[0], pal[1], pal[2], pal[3] };

            #pragma unroll
            for (int vg = 0; vg < 5; vg++) {
                const int vrow = kc*16 + ((lane >> 3) & 1) * 8 + (lane & 7);
                const int vcol = vg*16 + (lane >> 4) * 8;
                const uint32_t voff = (uint32_t)(vrow * APITCH + vcol * 2);
                uint32_t Vh4[4], Vl4[4];
                ldm_x4_t(Vh4, base + AVH + voff);
                ldm_x4_t(Vl4, base + AVL + voff);
                #pragma unroll
                for (int hh = 0; hh < 2; hh++) {
                    const int nb = vg*2 + hh;
                    mma16816(oacc[nb], Pa_h, Vh4[2*hh], Vh4[2*hh+1]);
                    mma16816(oacc[nb], Pa_l, Vh4[2*hh], Vh4[2*hh+1]);
                    mma16816(oacc[nb], Pa_h, Vl4[2*hh], Vl4[2*hh+1]);
                }
            }
        }
        __syncthreads();
    }

    // ---- finalize: normalize and write ch/cl ----
    const float inv0 = 1.f / l0, inv1 = 1.f / l1;
    const int s0 = qt*64 + w*16 + (lane >> 2);
    const int s1 = s0 + 8;
    #pragma unroll
    for (int nb = 0; nb < 10; nb++) {
        const int d = nb*8 + (lane & 3) * 2;
        {
            const size_t di = ((size_t)b * SQ + s0) * DM + h * HD + d;
            float o0 = oacc[nb][0] * inv0, o1 = oacc[nb][1] * inv0;
            __nv_bfloat16 h0 = __float2bfloat16_rn(o0);
            __nv_bfloat16 h1 = __float2bfloat16_rn(o1);
            *(__nv_bfloat162*)&ch_g[di] = __nv_bfloat162(h0, h1);
            *(__nv_bfloat162*)&cl_g[di] = __floats2bfloat162_rn(
                o0 - __bfloat162float(h0), o1 - __bfloat162float(h1));
        }
        {
            const size_t di = ((size_t)b * SQ + s1) * DM + h * HD + d;
            float o0 = oacc[nb][2] * inv1, o1 = oacc[nb][3] * inv1;
            __nv_bfloat16 h0 = __float2bfloat16_rn(o0);
            __nv_bfloat16 h1 = __float2bfloat16_rn(o1);
            *(__nv_bfloat162*)&ch_g[di] = __nv_bfloat162(h0, h1);
            *(__nv_bfloat162*)&cl_g[di] = __floats2bfloat162_rn(
                o0 - __bfloat162float(h0), o1 - __bfloat162float(h1));
        }
    }
}

// ---------------------------------------------------------------------------
extern "C" void kernel_launch(void* const* d_in, const int* in_sizes, int n_in,
                              void* d_out, int out_size)
{
    (void)in_sizes; (void)n_in; (void)out_size;
    const float* x     = (const float*)d_in[0];
    const float* cosp  = (const float*)d_in[1];
    const float* sinp  = (const float*)d_in[2];
    const float* Wqkv  = (const float*)d_in[3];
    const float* bqkv  = (const float*)d_in[4];
    const float* Wproj = (const float*)d_in[5];
    const float* bproj = (const float*)d_in[6];
    float* out = (float*)d_out;

    cudaFuncSetAttribute(gemm_bf16<true>,
                         cudaFuncAttributeMaxDynamicSharedMemorySize, GEMM_DSMEM);
    cudaFuncSetAttribute(gemm_bf16<false>,
                         cudaFuncAttributeMaxDynamicSharedMemorySize, GEMM_DSMEM);
    cudaFuncSetAttribute(attn_tc,
                         cudaFuncAttributeMaxDynamicSharedMemorySize, ATTN_SMEM);

    __nv_bfloat16 *xh, *xl, *wqh, *wql, *wph, *wpl, *ch, *cl;
    cudaGetSymbolAddress((void**)&xh,  xh_g);
    cudaGetSymbolAddress((void**)&xl,  xl_g);
    cudaGetSymbolAddress((void**)&wqh, wqh_g);
    cudaGetSymbolAddress((void**)&wql, wql_g);
    cudaGetSymbolAddress((void**)&wph, wph_g);
    cudaGetSymbolAddress((void**)&wpl, wpl_g);
    cudaGetSymbolAddress((void**)&ch,  ch_g);
    cudaGetSymbolAddress((void**)&cl,  cl_g);

    // 0) splits
    split_kernel<<<(MTOT*DM/4 + 255)/256, 256>>>(x, xh, xl, MTOT*DM/4);
    split_kernel<<<(NQKV*DM/4 + 255)/256, 256>>>(Wqkv, wqh, wql, NQKV*DM/4);
    split_kernel<<<(DM*DM/4 + 255)/256, 256>>>(Wproj, wph, wpl, DM*DM/4);
    // 1) QKV GEMM: q,k fp32 head-major + v bf16 hi/lo
    gemm_bf16<true><<<dim3(NQKV/128, MTOT/128), 256, GEMM_DSMEM>>>(
        xh, xl, wqh, wql, bqkv, nullptr);
    // 2) RoPE -> qh/ql, kh/kl
    rope_kernel<<<(NB*NH*SQ*40)/256, 256>>>(cosp, sinp);
    // 3) attention -> ch/cl
    attn_tc<<<dim3(SQ/64, NB*NH), 128, ATTN_SMEM>>>();
    // 4) output projection
    gemm_bf16<false><<<dim3(DM/128, MTOT/128), 256, GEMM_DSMEM>>>(
        ch, cl, wph, wpl, bproj, out);
}